// round 1
// baseline (speedup 1.0000x reference)
#include <cuda_runtime.h>
#include <cuda_bf16.h>
#include <math.h>

// ---------------------------------------------------------------------------
// AttentiveFPConv: out = tanh(x@Wn + bn + aggr@Wg + bg)
//   where aggr[u] = sum_{e: row[e]==u} g[col[e]],
//         g[v]    = x[v] * sigmoid( (x@Wa + ba)[v] )
// N = 40000 nodes, E = 640000 edges, D = 128.
// ---------------------------------------------------------------------------

#define NODES_MAX 40000
#define DIM 128

__device__ float g_yn[NODES_MAX * DIM];    // x@Wn + bn
__device__ float g_ga[NODES_MAX * DIM];    // x * sigmoid(x@Wa + ba)
__device__ float g_aggr[NODES_MAX * DIM];  // scatter-add result
__device__ int   g_is64;                   // edge_index stored as int64?

// ---------------------------------------------------------------------------
// Zero the aggregation buffer
// ---------------------------------------------------------------------------
__global__ void zero_aggr_kernel(int total_f4) {
    int i = blockIdx.x * blockDim.x + threadIdx.x;
    if (i < total_f4) {
        ((float4*)g_aggr)[i] = make_float4(0.f, 0.f, 0.f, 0.f);
    }
}

// ---------------------------------------------------------------------------
// Detect whether edge_index is int64 (LE: odd int32 words all zero) or int32.
// Node ids < 40000 so for int64 the high words are exactly 0; for int32 the
// odd slots are random ids — probability all 32 are zero is (1/40000)^32.
// ---------------------------------------------------------------------------
__global__ void detect_idx_kernel(const int* __restrict__ ei32) {
    if (threadIdx.x == 0 && blockIdx.x == 0) {
        int is64 = 1;
        #pragma unroll
        for (int i = 0; i < 32; i++) {
            if (ei32[2 * i + 1] != 0) { is64 = 0; break; }
        }
        g_is64 = is64;
    }
}

// ---------------------------------------------------------------------------
// Tiled fp32 GEMM: out[m][n] = epilogue( sum_k A[m][k]*W[k][n] + bias[n] )
//   mode 0: out = acc + bias                      (y_n)
//   mode 1: out = extra[m][n] * sigmoid(acc+bias) (g,  extra = x)
//   mode 2: out = tanh(acc + bias + extra[m][n])  (final, extra = y_n)
// BM=64, BN=128(full D), BK=16, 256 threads, 8x4 per-thread microtile.
// ---------------------------------------------------------------------------
#define BM 64
#define BN 128
#define BK 16
#define AS_STRIDE 68   // padded to kill store bank conflicts, keeps 16B align

__global__ __launch_bounds__(256) void gemm128_fused(
    const float* __restrict__ A,
    const float* __restrict__ W,
    const float* __restrict__ bias,
    const float* __restrict__ extra,
    float* __restrict__ out,
    int N, int mode)
{
    __shared__ __align__(16) float As[BK * AS_STRIDE];  // [k][m] transposed
    __shared__ __align__(16) float Bs[BK * BN];         // [k][n]

    const int tid = threadIdx.x;
    const int m0  = blockIdx.x * BM;
    const int mt  = tid >> 5;          // 0..7  (row group)
    const int nt  = tid & 31;          // 0..31 (col group)

    // A-tile load mapping: one float4 per thread per k-chunk
    const int a_row = tid >> 2;             // 0..63
    const int a_col = (tid & 3) << 2;       // 0,4,8,12
    // B-tile load mapping: two float4 per thread per k-chunk
    const int b_row = tid >> 5;             // 0..7 (also +8)
    const int b_col = (tid & 31) << 2;      // 0..124

    float acc[8][4];
    #pragma unroll
    for (int i = 0; i < 8; i++)
        #pragma unroll
        for (int j = 0; j < 4; j++) acc[i][j] = 0.f;

    const int rA = min(m0 + a_row, N - 1);  // clamp (N divisible by 64 anyway)

    for (int k0 = 0; k0 < DIM; k0 += BK) {
        float4 av = *(const float4*)(A + (size_t)rA * DIM + k0 + a_col);
        As[(a_col + 0) * AS_STRIDE + a_row] = av.x;
        As[(a_col + 1) * AS_STRIDE + a_row] = av.y;
        As[(a_col + 2) * AS_STRIDE + a_row] = av.z;
        As[(a_col + 3) * AS_STRIDE + a_row] = av.w;

        float4 b0 = *(const float4*)(W + (size_t)(k0 + b_row) * DIM + b_col);
        float4 b1 = *(const float4*)(W + (size_t)(k0 + b_row + 8) * DIM + b_col);
        *(float4*)&Bs[b_row * BN + b_col]       = b0;
        *(float4*)&Bs[(b_row + 8) * BN + b_col] = b1;

        __syncthreads();

        #pragma unroll
        for (int kk = 0; kk < BK; kk++) {
            float4 a0 = *(const float4*)&As[kk * AS_STRIDE + mt * 8];
            float4 a1 = *(const float4*)&As[kk * AS_STRIDE + mt * 8 + 4];
            float4 bv = *(const float4*)&Bs[kk * BN + nt * 4];
            float ar[8] = {a0.x, a0.y, a0.z, a0.w, a1.x, a1.y, a1.z, a1.w};
            float br[4] = {bv.x, bv.y, bv.z, bv.w};
            #pragma unroll
            for (int i = 0; i < 8; i++)
                #pragma unroll
                for (int j = 0; j < 4; j++)
                    acc[i][j] = fmaf(ar[i], br[j], acc[i][j]);
        }
        __syncthreads();
    }

    const float4 bb = *(const float4*)(bias + nt * 4);

    #pragma unroll
    for (int i = 0; i < 8; i++) {
        int m = m0 + mt * 8 + i;
        if (m >= N) break;
        float4 r;
        r.x = acc[i][0] + bb.x;
        r.y = acc[i][1] + bb.y;
        r.z = acc[i][2] + bb.z;
        r.w = acc[i][3] + bb.w;
        if (mode == 1) {
            float4 xv = *(const float4*)(extra + (size_t)m * DIM + nt * 4);
            r.x = xv.x * (1.f / (1.f + expf(-r.x)));
            r.y = xv.y * (1.f / (1.f + expf(-r.y)));
            r.z = xv.z * (1.f / (1.f + expf(-r.z)));
            r.w = xv.w * (1.f / (1.f + expf(-r.w)));
        } else if (mode == 2) {
            float4 yv = *(const float4*)(extra + (size_t)m * DIM + nt * 4);
            r.x = tanhf(r.x + yv.x);
            r.y = tanhf(r.y + yv.y);
            r.z = tanhf(r.z + yv.z);
            r.w = tanhf(r.w + yv.w);
        }
        *(float4*)(out + (size_t)m * DIM + nt * 4) = r;
    }
}

// ---------------------------------------------------------------------------
// Edge scatter: aggr[row[e]] += g[col[e]]   (atomic fp32 RED)
// One thread per (edge, float4-of-dims): 32 threads per edge.
// ---------------------------------------------------------------------------
__global__ __launch_bounds__(256) void edge_scatter_kernel(
    const void* __restrict__ ei, int E)
{
    long long t = (long long)blockIdx.x * blockDim.x + threadIdx.x;
    int e = (int)(t >> 5);
    if (e >= E) return;
    int q = ((int)t & 31) << 2;  // dim offset 0..124

    int row, col;
    if (g_is64) {
        const long long* p = (const long long*)ei;
        row = (int)p[e];
        col = (int)p[E + e];
    } else {
        const int* p = (const int*)ei;
        row = p[e];
        col = p[E + e];
    }

    float4 v = *(const float4*)(g_ga + (size_t)col * DIM + q);
    float* dst = g_aggr + (size_t)row * DIM + q;
    atomicAdd(dst + 0, v.x);
    atomicAdd(dst + 1, v.y);
    atomicAdd(dst + 2, v.z);
    atomicAdd(dst + 3, v.w);
}

// ---------------------------------------------------------------------------
// Launch
// ---------------------------------------------------------------------------
extern "C" void kernel_launch(void* const* d_in, const int* in_sizes, int n_in,
                              void* d_out, int out_size)
{
    const float* x    = (const float*)d_in[0];
    const void*  ei   = d_in[1];
    const float* Wn_w = (const float*)d_in[2];
    const float* Wn_b = (const float*)d_in[3];
    const float* Wg_w = (const float*)d_in[4];
    const float* Wg_b = (const float*)d_in[5];
    const float* Wa_w = (const float*)d_in[6];
    const float* Wa_b = (const float*)d_in[7];
    float* out = (float*)d_out;

    const int N = in_sizes[0] / DIM;   // 40000
    const int E = in_sizes[1] / 2;     // 640000 (element count same for i32/i64)

    float *p_yn, *p_ga, *p_aggr;
    cudaGetSymbolAddress((void**)&p_yn,   g_yn);
    cudaGetSymbolAddress((void**)&p_ga,   g_ga);
    cudaGetSymbolAddress((void**)&p_aggr, g_aggr);

    // 1. zero aggr
    {
        int total_f4 = N * DIM / 4;
        zero_aggr_kernel<<<(total_f4 + 255) / 256, 256>>>(total_f4);
    }
    // 2. detect index dtype
    detect_idx_kernel<<<1, 32>>>((const int*)ei);

    // 3. y_n = x@Wn + bn
    gemm128_fused<<<(N + BM - 1) / BM, 256>>>(x, Wn_w, Wn_b, nullptr, p_yn, N, 0);
    // 4. g = x * sigmoid(x@Wa + ba)
    gemm128_fused<<<(N + BM - 1) / BM, 256>>>(x, Wa_w, Wa_b, x, p_ga, N, 1);

    // 5. aggr[row] += g[col]
    {
        long long threads = (long long)E * 32;
        int blocks = (int)((threads + 255) / 256);
        edge_scatter_kernel<<<blocks, 256>>>(ei, E);
    }

    // 6. out = tanh(aggr@Wg + bg + y_n)
    gemm128_fused<<<(N + BM - 1) / BM, 256>>>(p_aggr, Wg_w, Wg_b, p_yn, out, N, 2);
}

// round 2
// speedup vs baseline: 1.3547x; 1.3547x over previous
#include <cuda_runtime.h>
#include <cuda_bf16.h>
#include <math.h>

// ---------------------------------------------------------------------------
// AttentiveFPConv: out = tanh(x@Wn + bn + aggr@Wg + bg)
//   aggr[u] = sum_{e: row[e]==u} g[col[e]],  g[v] = x[v] * sigmoid((x@Wa+ba)[v])
// N = 40000, E = 640000, D = 128.
// ---------------------------------------------------------------------------

#define NODES_MAX 40000
#define EDGES_MAX 640000
#define DIM 128

__device__ float g_yn[NODES_MAX * DIM];
__device__ float g_ga[NODES_MAX * DIM];
__device__ float g_aggr[NODES_MAX * DIM];
__device__ int2  g_eidx[EDGES_MAX];      // packed (row, col) as int32
__device__ int   g_is64;

// ---------------------------------------------------------------------------
__global__ void zero_aggr_kernel(int total_f4) {
    int i = blockIdx.x * blockDim.x + threadIdx.x;
    if (i < total_f4)
        ((float4*)g_aggr)[i] = make_float4(0.f, 0.f, 0.f, 0.f);
}

// Detect int64 vs int32 edge_index (LE high words all zero for ids < 2^31).
__global__ void detect_idx_kernel(const int* __restrict__ ei32) {
    if (threadIdx.x == 0 && blockIdx.x == 0) {
        int is64 = 1;
        #pragma unroll
        for (int i = 0; i < 32; i++)
            if (ei32[2 * i + 1] != 0) { is64 = 0; break; }
        g_is64 = is64;
    }
}

// Pack edge indices into int2 (row, col).
__global__ __launch_bounds__(256) void pack_idx_kernel(const void* __restrict__ ei, int E) {
    int e = blockIdx.x * blockDim.x + threadIdx.x;
    if (e >= E) return;
    int row, col;
    if (g_is64) {
        const long long* p = (const long long*)ei;
        row = (int)p[e];
        col = (int)p[E + e];
    } else {
        const int* p = (const int*)ei;
        row = p[e];
        col = p[E + e];
    }
    g_eidx[e] = make_int2(row, col);
}

// ---------------------------------------------------------------------------
// 128x128 tile GEMM, 256 threads, 8x8 microtile, BK=16.
//   mode 0: out = acc + bias
//   mode 1: out = extra * sigmoid(acc + bias)
//   mode 2: out = tanh(acc + bias + extra)
// ---------------------------------------------------------------------------
#define GBM 128
#define GBN 128
#define GBK 16
#define AS_PAD 4

__global__ __launch_bounds__(256, 2) void gemm128x128_fused(
    const float* __restrict__ A,
    const float* __restrict__ W,
    const float* __restrict__ bias,
    const float* __restrict__ extra,
    float* __restrict__ out,
    int N, int mode)
{
    __shared__ __align__(16) float As[GBK][GBM + AS_PAD];  // [k][m]
    __shared__ __align__(16) float Bs[GBK][GBN];           // [k][n]

    const int tid = threadIdx.x;
    const int m0  = blockIdx.x * GBM;
    const int tx  = tid & 15;   // col group (0..15)
    const int ty  = tid >> 4;   // row group (0..15)

    // A load: row = tid>>1 (0..127), k-offset = (tid&1)*8  -> 2 float4 per iter
    const int a_row = tid >> 1;
    const int a_k   = (tid & 1) * 8;
    int rA = m0 + a_row; if (rA >= N) rA = N - 1;
    // B load: row = tid>>4 (0..15), col = (tid&15)*4 and +64
    const int b_row = tid >> 4;
    const int b_c   = (tid & 15) * 4;

    float acc[8][8];
    #pragma unroll
    for (int i = 0; i < 8; i++)
        #pragma unroll
        for (int j = 0; j < 8; j++) acc[i][j] = 0.f;

    for (int k0 = 0; k0 < DIM; k0 += GBK) {
        float4 av0 = *(const float4*)(A + (size_t)rA * DIM + k0 + a_k);
        float4 av1 = *(const float4*)(A + (size_t)rA * DIM + k0 + a_k + 4);
        As[a_k + 0][a_row] = av0.x;
        As[a_k + 1][a_row] = av0.y;
        As[a_k + 2][a_row] = av0.z;
        As[a_k + 3][a_row] = av0.w;
        As[a_k + 4][a_row] = av1.x;
        As[a_k + 5][a_row] = av1.y;
        As[a_k + 6][a_row] = av1.z;
        As[a_k + 7][a_row] = av1.w;

        float4 bv0 = *(const float4*)(W + (size_t)(k0 + b_row) * DIM + b_c);
        float4 bv1 = *(const float4*)(W + (size_t)(k0 + b_row) * DIM + b_c + 64);
        *(float4*)&Bs[b_row][b_c]      = bv0;
        *(float4*)&Bs[b_row][b_c + 64] = bv1;

        __syncthreads();

        #pragma unroll
        for (int kk = 0; kk < GBK; kk++) {
            float4 a0 = *(const float4*)&As[kk][ty * 4];
            float4 a1 = *(const float4*)&As[kk][64 + ty * 4];
            float4 b0 = *(const float4*)&Bs[kk][tx * 4];
            float4 b1 = *(const float4*)&Bs[kk][64 + tx * 4];
            float ar[8] = {a0.x, a0.y, a0.z, a0.w, a1.x, a1.y, a1.z, a1.w};
            float br[8] = {b0.x, b0.y, b0.z, b0.w, b1.x, b1.y, b1.z, b1.w};
            #pragma unroll
            for (int i = 0; i < 8; i++)
                #pragma unroll
                for (int j = 0; j < 8; j++)
                    acc[i][j] = fmaf(ar[i], br[j], acc[i][j]);
        }
        __syncthreads();
    }

    const float4 bb0 = *(const float4*)(bias + tx * 4);
    const float4 bb1 = *(const float4*)(bias + 64 + tx * 4);
    const float bbr[8] = {bb0.x, bb0.y, bb0.z, bb0.w, bb1.x, bb1.y, bb1.z, bb1.w};

    #pragma unroll
    for (int i = 0; i < 8; i++) {
        int m = m0 + ((i < 4) ? (ty * 4 + i) : (64 + ty * 4 + i - 4));
        if (m >= N) continue;
        float r[8];
        #pragma unroll
        for (int j = 0; j < 8; j++) r[j] = acc[i][j] + bbr[j];

        if (mode == 1) {
            const float* xp = extra + (size_t)m * DIM;
            float4 x0 = *(const float4*)(xp + tx * 4);
            float4 x1 = *(const float4*)(xp + 64 + tx * 4);
            float xr[8] = {x0.x, x0.y, x0.z, x0.w, x1.x, x1.y, x1.z, x1.w};
            #pragma unroll
            for (int j = 0; j < 8; j++)
                r[j] = xr[j] * (1.f / (1.f + expf(-r[j])));
        } else if (mode == 2) {
            const float* yp = extra + (size_t)m * DIM;
            float4 y0 = *(const float4*)(yp + tx * 4);
            float4 y1 = *(const float4*)(yp + 64 + tx * 4);
            float yr[8] = {y0.x, y0.y, y0.z, y0.w, y1.x, y1.y, y1.z, y1.w};
            #pragma unroll
            for (int j = 0; j < 8; j++)
                r[j] = tanhf(r[j] + yr[j]);
        }
        *(float4*)(out + (size_t)m * DIM + tx * 4)      = make_float4(r[0], r[1], r[2], r[3]);
        *(float4*)(out + (size_t)m * DIM + 64 + tx * 4) = make_float4(r[4], r[5], r[6], r[7]);
    }
}

// ---------------------------------------------------------------------------
// Edge scatter: one warp per edge, one red.global.add.v4.f32 per lane (16B).
// ---------------------------------------------------------------------------
__global__ __launch_bounds__(256) void edge_scatter_kernel(int E)
{
    int warp = (int)((blockIdx.x * 256 + threadIdx.x) >> 5);
    if (warp >= E) return;
    int lane = threadIdx.x & 31;

    int2 rc = g_eidx[warp];                 // broadcast across warp
    const float* src = g_ga + (size_t)rc.y * DIM + lane * 4;
    float* dst       = g_aggr + (size_t)rc.x * DIM + lane * 4;

    float4 v = *(const float4*)src;
    asm volatile("red.global.add.v4.f32 [%0], {%1, %2, %3, %4};"
                 :: "l"(dst), "f"(v.x), "f"(v.y), "f"(v.z), "f"(v.w)
                 : "memory");
}

// ---------------------------------------------------------------------------
extern "C" void kernel_launch(void* const* d_in, const int* in_sizes, int n_in,
                              void* d_out, int out_size)
{
    const float* x    = (const float*)d_in[0];
    const void*  ei   = d_in[1];
    const float* Wn_w = (const float*)d_in[2];
    const float* Wn_b = (const float*)d_in[3];
    const float* Wg_w = (const float*)d_in[4];
    const float* Wg_b = (const float*)d_in[5];
    const float* Wa_w = (const float*)d_in[6];
    const float* Wa_b = (const float*)d_in[7];
    float* out = (float*)d_out;

    const int N = in_sizes[0] / DIM;
    const int E = in_sizes[1] / 2;

    float *p_yn, *p_ga, *p_aggr;
    cudaGetSymbolAddress((void**)&p_yn,   g_yn);
    cudaGetSymbolAddress((void**)&p_ga,   g_ga);
    cudaGetSymbolAddress((void**)&p_aggr, g_aggr);

    // 1. zero aggr
    {
        int total_f4 = N * DIM / 4;
        zero_aggr_kernel<<<(total_f4 + 255) / 256, 256>>>(total_f4);
    }
    // 2. detect + pack indices
    detect_idx_kernel<<<1, 32>>>((const int*)ei);
    pack_idx_kernel<<<(E + 255) / 256, 256>>>(ei, E);

    int gblocks = (N + GBM - 1) / GBM;
    // 3. y_n = x@Wn + bn
    gemm128x128_fused<<<gblocks, 256>>>(x, Wn_w, Wn_b, nullptr, p_yn, N, 0);
    // 4. g = x * sigmoid(x@Wa + ba)
    gemm128x128_fused<<<gblocks, 256>>>(x, Wa_w, Wa_b, x, p_ga, N, 1);

    // 5. aggr[row] += g[col]  (warp per edge, vector RED)
    {
        long long threads = (long long)E * 32;
        int blocks = (int)((threads + 255) / 256);
        edge_scatter_kernel<<<blocks, 256>>>(E);
    }

    // 6. out = tanh(aggr@Wg + bg + y_n)
    gemm128x128_fused<<<gblocks, 256>>>(p_aggr, Wg_w, Wg_b, p_yn, out, N, 2);
}